// round 10
// baseline (speedup 1.0000x reference)
#include <cuda_runtime.h>

#define NB 262144
#define NTHREADS (NB / 2)   // each thread: 2 elements (feature-pair packed)
#define BLOCK 128

typedef unsigned long long u64;

__device__ __forceinline__ u64 pack2(float lo, float hi) {
    u64 r; asm("mov.b64 %0, {%1,%2};" : "=l"(r) : "f"(lo), "f"(hi)); return r;
}
__device__ __forceinline__ void unpack2(u64 v, float& lo, float& hi) {
    asm("mov.b64 {%0,%1}, %2;" : "=f"(lo), "=f"(hi) : "l"(v));
}
__device__ __forceinline__ u64 fma2(u64 a, u64 b, u64 c) {
    u64 r; asm("fma.rn.f32x2 %0, %1, %2, %3;" : "=l"(r) : "l"(a), "l"(b), "l"(c)); return r;
}
__device__ __forceinline__ u64 mul2(u64 a, u64 b) {
    u64 r; asm("mul.rn.f32x2 %0, %1, %2;" : "=l"(r) : "l"(a), "l"(b)); return r;
}
__device__ __forceinline__ u64 relu2(u64 x) {
    float lo, hi; unpack2(x, lo, hi);
    lo = fmaxf(lo, 0.0f); hi = fmaxf(hi, 0.0f);
    return pack2(lo, hi);
}

__global__ __launch_bounds__(BLOCK, 7)   // 7 blocks/SM -> grid 1024 fully resident, single wave
void hybridq_kernel(const float* __restrict__ xq, const float* __restrict__ xc,
                    const float* __restrict__ qp,
                    const float* __restrict__ W1, const float* __restrict__ b1,
                    const float* __restrict__ W2, const float* __restrict__ b2,
                    const float* __restrict__ W3, const float* __restrict__ b3,
                    float* __restrict__ out)
{
    // Feature-pair-packed weights: each u64 holds TWO DISTINCT weights.
    // All lanes read identical SMEM addresses -> broadcast LDS.
    __shared__ u64 sW1[32][8];   // [k][pair j] = (W1[1+2j][k], W1[2+2j][k])
    __shared__ u64 sWqb[32];     // (W1[0][k], b1[k])  -- pairs with input (q, 1)
    __shared__ u64 sW2[32 * 8];  // W2 native row-major viewed as u64 pairs
    __shared__ u64 sW3[8];       // W3 native pairs
    __shared__ u64 sb2[8];       // b2 native pairs

    const int tid = threadIdx.x;
    for (int i = tid; i < 32 * 8; i += BLOCK) {
        int k = i / 8, j = i % 8;
        sW1[k][j] = pack2(W1[(1 + 2 * j) * 32 + k], W1[(2 + 2 * j) * 32 + k]);
    }
    for (int i = tid; i < 32 * 8; i += BLOCK)
        sW2[i] = ((const u64*)W2)[i];
    if (tid < 32) sWqb[tid] = pack2(W1[tid], b1[tid]);   // (W1[0][k], b1[k])
    if (tid < 8) {
        sW3[tid] = ((const u64*)W3)[tid];
        sb2[tid] = ((const u64*)b2)[tid];
    }
    __syncthreads();

    const int t  = blockIdx.x * BLOCK + tid;
    const int e0 = t;
    const int e1 = t + NTHREADS;

    const float bb = __ldg(b3);   // issue early, long-latency scalar

    // ---- Quantum feature: <Z0> = prod_{i=1..6} cos(x_q[i] + qp[i]) ----
    // (CNOT-ring GF(2): qubit-0 output = parity(b1..b6); per-qubit factor
    //  cos^2(h)-sin^2(h) = cos(2h) = cos(x+w); qubit 0's own angle cancels.)
    float q0 = 1.0f, q1 = 1.0f;
#pragma unroll
    for (int i = 1; i < 7; i++) {
        float w = __ldg(qp + i);
        q0 *= __cosf(__ldg(xq + (size_t)e0 * 7 + i) + w);
        q1 *= __cosf(__ldg(xq + (size_t)e1 * 7 + i) + w);
    }

    // ---- Inputs: 8 native xc pairs + (q, 1) pair (bias folded as feature) ----
    u64 in[2][9];
    in[0][8] = pack2(q0, 1.0f);
    in[1][8] = pack2(q1, 1.0f);
    {
        const ulonglong2* c0 = (const ulonglong2*)(xc + (size_t)e0 * 16);
        const ulonglong2* c1 = (const ulonglong2*)(xc + (size_t)e1 * 16);
#pragma unroll
        for (int p = 0; p < 4; p++) {
            ulonglong2 a = c0[p]; in[0][2 * p] = a.x; in[0][2 * p + 1] = a.y;
            ulonglong2 b = c1[p]; in[1][2 * p] = b.x; in[1][2 * p + 1] = b.y;
        }
    }

    // ---- h2 accumulators: 8 output-pairs per element, init with b2 ----
    u64 h2[2][8];
#pragma unroll
    for (int e = 0; e < 2; e++)
#pragma unroll
        for (int j = 0; j < 8; j++)
            h2[e][j] = sb2[j];

    // ---- Fused layers 1+2 ----
#pragma unroll 2
    for (int k = 0; k < 32; k++) {
        const ulonglong2* r1 = (const ulonglong2*)&sW1[k][0];
        ulonglong2 w01 = r1[0];
        ulonglong2 w23 = r1[1];
        ulonglong2 w45 = r1[2];
        ulonglong2 w67 = r1[3];
        u64 wqb = sWqb[k];

        u64 a2[2];
#pragma unroll
        for (int e = 0; e < 2; e++) {
            u64 acc = mul2(in[e][0], w01.x);
            acc = fma2(in[e][1], w01.y, acc);
            acc = fma2(in[e][2], w23.x, acc);
            acc = fma2(in[e][3], w23.y, acc);
            acc = fma2(in[e][4], w45.x, acc);
            acc = fma2(in[e][5], w45.y, acc);
            acc = fma2(in[e][6], w67.x, acc);
            acc = fma2(in[e][7], w67.y, acc);
            acc = fma2(in[e][8], wqb, acc);   // q*W1q + 1*b1 folded in
            float lo, hi;
            unpack2(acc, lo, hi);             // free: register pair
            float s = fmaxf(lo + hi, 0.0f);
            a2[e] = pack2(s, s);
        }

        const ulonglong2* r2 = (const ulonglong2*)&sW2[k * 8];
        ulonglong2 v01 = r2[0];
        ulonglong2 v23 = r2[1];
        ulonglong2 v45 = r2[2];
        ulonglong2 v67 = r2[3];
#pragma unroll
        for (int e = 0; e < 2; e++) {
            h2[e][0] = fma2(a2[e], v01.x, h2[e][0]);
            h2[e][1] = fma2(a2[e], v01.y, h2[e][1]);
            h2[e][2] = fma2(a2[e], v23.x, h2[e][2]);
            h2[e][3] = fma2(a2[e], v23.y, h2[e][3]);
            h2[e][4] = fma2(a2[e], v45.x, h2[e][4]);
            h2[e][5] = fma2(a2[e], v45.y, h2[e][5]);
            h2[e][6] = fma2(a2[e], v67.x, h2[e][6]);
            h2[e][7] = fma2(a2[e], v67.y, h2[e][7]);
        }
    }

    // ---- Layer 3: relu(h2) . W3 + b3, pairwise then hsum ----
#pragma unroll
    for (int e = 0; e < 2; e++) {
        u64 acc = mul2(relu2(h2[e][0]), sW3[0]);
#pragma unroll
        for (int j = 1; j < 8; j++)
            acc = fma2(relu2(h2[e][j]), sW3[j], acc);
        float lo, hi;
        unpack2(acc, lo, hi);
        out[t + e * NTHREADS] = bb + lo + hi;
    }
}

extern "C" void kernel_launch(void* const* d_in, const int* in_sizes, int n_in,
                              void* d_out, int out_size)
{
    const float* xq = (const float*)d_in[0];
    const float* xc = (const float*)d_in[1];
    const float* qp = (const float*)d_in[2];
    const float* W1 = (const float*)d_in[3];
    const float* b1 = (const float*)d_in[4];
    const float* W2 = (const float*)d_in[5];
    const float* b2 = (const float*)d_in[6];
    const float* W3 = (const float*)d_in[7];
    const float* b3 = (const float*)d_in[8];
    float* out = (float*)d_out;

    hybridq_kernel<<<NTHREADS / BLOCK, BLOCK>>>(xq, xc, qp, W1, b1, W2, b2, W3, b3, out);
}

// round 11
// speedup vs baseline: 1.8346x; 1.8346x over previous
#include <cuda_runtime.h>

#define NB 262144
#define NTHREADS (NB / 2)   // each thread: 2 elements (feature-pair packed)
#define BLOCK 128

typedef unsigned long long u64;

struct CW {
    ulonglong2 W1[32][4];   // [k][j2]: 4 weight-pairs = features (1,2)(3,4)... per 16B
    ulonglong2 W2[32][4];   // [k][j2]: output pairs, native W2 row-major
    u64 wqb[32];            // (W1[0][k], b1[k]) — pairs with input (q, 1)
    u64 W3[8];              // native pairs
    u64 b2[8];              // native pairs
    float b3;
    float pad;
};

__constant__ CW cw;
__device__ CW d_stage;

__device__ __forceinline__ u64 pack2(float lo, float hi) {
    u64 r; asm("mov.b64 %0, {%1,%2};" : "=l"(r) : "f"(lo), "f"(hi)); return r;
}
__device__ __forceinline__ void unpack2(u64 v, float& lo, float& hi) {
    asm("mov.b64 {%0,%1}, %2;" : "=f"(lo), "=f"(hi) : "l"(v));
}
__device__ __forceinline__ u64 fma2(u64 a, u64 b, u64 c) {
    u64 r; asm("fma.rn.f32x2 %0, %1, %2, %3;" : "=l"(r) : "l"(a), "l"(b), "l"(c)); return r;
}
__device__ __forceinline__ u64 mul2(u64 a, u64 b) {
    u64 r; asm("mul.rn.f32x2 %0, %1, %2;" : "=l"(r) : "l"(a), "l"(b)); return r;
}
__device__ __forceinline__ u64 relu2(u64 x) {
    float lo, hi; unpack2(x, lo, hi);
    lo = fmaxf(lo, 0.0f); hi = fmaxf(hi, 0.0f);
    return pack2(lo, hi);
}

__global__ void prep_kernel(const float* __restrict__ W1, const float* __restrict__ b1,
                            const float* __restrict__ W2, const float* __restrict__ b2,
                            const float* __restrict__ W3, const float* __restrict__ b3)
{
    const int tid = threadIdx.x;
    for (int i = tid; i < 32 * 4; i += blockDim.x) {
        int k = i / 4, j2 = i % 4;
        ulonglong2 a;
        a.x = pack2(W1[(1 + 4 * j2) * 32 + k], W1[(2 + 4 * j2) * 32 + k]);
        a.y = pack2(W1[(3 + 4 * j2) * 32 + k], W1[(4 + 4 * j2) * 32 + k]);
        d_stage.W1[k][j2] = a;
        ulonglong2 b;
        b.x = ((const u64*)W2)[k * 8 + 2 * j2];
        b.y = ((const u64*)W2)[k * 8 + 2 * j2 + 1];
        d_stage.W2[k][j2] = b;
    }
    if (tid < 32) d_stage.wqb[tid] = pack2(W1[tid], b1[tid]);
    if (tid < 8) {
        d_stage.W3[tid] = ((const u64*)W3)[tid];
        d_stage.b2[tid] = ((const u64*)b2)[tid];
    }
    if (tid == 0) d_stage.b3 = b3[0];
}

__global__ __launch_bounds__(BLOCK, 5)
void hybridq_kernel(const float* __restrict__ xq, const float* __restrict__ xc,
                    const float* __restrict__ qp, float* __restrict__ out)
{
    const int t  = blockIdx.x * BLOCK + threadIdx.x;
    const int e0 = t;
    const int e1 = t + NTHREADS;

    // ---- Quantum feature: <Z0> = prod_{i=1..6} cos(x_q[i] + qp[i]) ----
    // (CNOT-ring GF(2): qubit-0 output = parity(b1..b6); per-qubit factor
    //  cos^2(h)-sin^2(h) = cos(2h) = cos(x+w); qubit 0's own angle cancels.)
    float q0 = 1.0f, q1 = 1.0f;
#pragma unroll
    for (int i = 1; i < 7; i++) {
        float w = __ldg(qp + i);
        q0 *= __cosf(__ldg(xq + (size_t)e0 * 7 + i) + w);
        q1 *= __cosf(__ldg(xq + (size_t)e1 * 7 + i) + w);
    }

    // ---- Inputs: 8 native xc pairs + (q, 1) pair (bias folded as feature) ----
    u64 in[2][9];
    in[0][8] = pack2(q0, 1.0f);
    in[1][8] = pack2(q1, 1.0f);
    {
        const ulonglong2* c0 = (const ulonglong2*)(xc + (size_t)e0 * 16);
        const ulonglong2* c1 = (const ulonglong2*)(xc + (size_t)e1 * 16);
#pragma unroll
        for (int p = 0; p < 4; p++) {
            ulonglong2 a = c0[p]; in[0][2 * p] = a.x; in[0][2 * p + 1] = a.y;
            ulonglong2 b = c1[p]; in[1][2 * p] = b.x; in[1][2 * p + 1] = b.y;
        }
    }

    // ---- h2 accumulators: 8 output-pairs per element, init with b2 (const) ----
    u64 h2[2][8];
#pragma unroll
    for (int e = 0; e < 2; e++)
#pragma unroll
        for (int j = 0; j < 8; j++)
            h2[e][j] = cw.b2[j];

    // ---- Fused layers 1+2; all weights from the constant bank (LDC port) ----
#pragma unroll 2
    for (int k = 0; k < 32; k++) {
        ulonglong2 w01 = cw.W1[k][0];
        ulonglong2 w23 = cw.W1[k][1];
        ulonglong2 w45 = cw.W1[k][2];
        ulonglong2 w67 = cw.W1[k][3];
        u64 wqb = cw.wqb[k];

        u64 a2[2];
#pragma unroll
        for (int e = 0; e < 2; e++) {
            u64 acc = mul2(in[e][0], w01.x);
            acc = fma2(in[e][1], w01.y, acc);
            acc = fma2(in[e][2], w23.x, acc);
            acc = fma2(in[e][3], w23.y, acc);
            acc = fma2(in[e][4], w45.x, acc);
            acc = fma2(in[e][5], w45.y, acc);
            acc = fma2(in[e][6], w67.x, acc);
            acc = fma2(in[e][7], w67.y, acc);
            acc = fma2(in[e][8], wqb, acc);   // q*W1q + 1*b1 folded in
            float lo, hi;
            unpack2(acc, lo, hi);             // free: register pair
            float s = fmaxf(lo + hi, 0.0f);
            a2[e] = pack2(s, s);
        }

        ulonglong2 v01 = cw.W2[k][0];
        ulonglong2 v23 = cw.W2[k][1];
        ulonglong2 v45 = cw.W2[k][2];
        ulonglong2 v67 = cw.W2[k][3];
#pragma unroll
        for (int e = 0; e < 2; e++) {
            h2[e][0] = fma2(a2[e], v01.x, h2[e][0]);
            h2[e][1] = fma2(a2[e], v01.y, h2[e][1]);
            h2[e][2] = fma2(a2[e], v23.x, h2[e][2]);
            h2[e][3] = fma2(a2[e], v23.y, h2[e][3]);
            h2[e][4] = fma2(a2[e], v45.x, h2[e][4]);
            h2[e][5] = fma2(a2[e], v45.y, h2[e][5]);
            h2[e][6] = fma2(a2[e], v67.x, h2[e][6]);
            h2[e][7] = fma2(a2[e], v67.y, h2[e][7]);
        }
    }

    // ---- Layer 3: relu(h2) . W3 + b3, pairwise then hsum ----
    const float bb = cw.b3;
#pragma unroll
    for (int e = 0; e < 2; e++) {
        u64 acc = mul2(relu2(h2[e][0]), cw.W3[0]);
#pragma unroll
        for (int j = 1; j < 8; j++)
            acc = fma2(relu2(h2[e][j]), cw.W3[j], acc);
        float lo, hi;
        unpack2(acc, lo, hi);
        out[t + e * NTHREADS] = bb + lo + hi;
    }
}

extern "C" void kernel_launch(void* const* d_in, const int* in_sizes, int n_in,
                              void* d_out, int out_size)
{
    const float* xq = (const float*)d_in[0];
    const float* xc = (const float*)d_in[1];
    const float* qp = (const float*)d_in[2];
    const float* W1 = (const float*)d_in[3];
    const float* b1 = (const float*)d_in[4];
    const float* W2 = (const float*)d_in[5];
    const float* b2 = (const float*)d_in[6];
    const float* W3 = (const float*)d_in[7];
    const float* b3 = (const float*)d_in[8];
    float* out = (float*)d_out;

    // 1. Pack weights into the staging struct (device).
    prep_kernel<<<1, 128>>>(W1, b1, W2, b2, W3, b3);

    // 2. Staging -> constant bank (D2D async memcpy; graph-capturable node).
    void* stage_ptr = nullptr;
    cudaGetSymbolAddress(&stage_ptr, d_stage);
    cudaMemcpyToSymbolAsync(cw, stage_ptr, sizeof(CW), 0, cudaMemcpyDeviceToDevice, 0);

    // 3. Main kernel: weights ride the constant-cache port, L1 carries only I/O.
    hybridq_kernel<<<NTHREADS / BLOCK, BLOCK>>>(xq, xc, qp, out);
}